// round 14
// baseline (speedup 1.0000x reference)
#include <cuda_runtime.h>
#include <cuda_fp16.h>
#include <math.h>
#include <stdint.h>

#define TT 1024
#define HH 2048
#define EE 16
#define KTOP 4
#define II 1408
#define ISH 2816

// ---------------- fp32 scratch ----------------
__device__ float g_gu[(size_t)TT * KTOP * 2 * II];
__device__ float g_downbuf[(size_t)TT * KTOP * HH];
__device__ float g_sgu[(size_t)TT * 2 * ISH];
__device__ float g_shdown[(size_t)TT * HH];
__device__ int   g_counts[EE];
__device__ int   g_list[EE * TT];
__device__ float g_tw[TT * KTOP];

// ---------------- fp16 scratch ----------------
__device__ __half g_act_h[(size_t)TT * KTOP * II];
__device__ __half g_shact_h[(size_t)TT * ISH];
__device__ __half g_x_h[(size_t)TT * HH];

__device__ __forceinline__ float* fbuf_ptr(int sel) {
    switch (sel) {
        case 2: return g_downbuf;
        case 3: return g_sgu;
        case 5: return g_shdown;
        default: return g_gu;
    }
}
__device__ __forceinline__ __half* hbuf_ptr(int sel) {
    switch (sel) {
        case 1: return g_shact_h;
        case 2: return g_x_h;
        default: return g_act_h;
    }
}

// ---------------- helpers ----------------
__device__ __forceinline__ uint32_t smem_u32(const void* p) {
    uint32_t a;
    asm("{ .reg .u64 t; cvta.to.shared.u64 t, %1; cvt.u32.u64 %0, t; }" : "=r"(a) : "l"(p));
    return a;
}
__device__ __forceinline__ void ldsm4(uint32_t* r, uint32_t addr) {
    asm volatile("ldmatrix.sync.aligned.m8n8.x4.shared.b16 {%0,%1,%2,%3}, [%4];"
                 : "=r"(r[0]), "=r"(r[1]), "=r"(r[2]), "=r"(r[3]) : "r"(addr));
}
__device__ __forceinline__ void ldsm4t(uint32_t* r, uint32_t addr) {
    asm volatile("ldmatrix.sync.aligned.m8n8.x4.trans.shared.b16 {%0,%1,%2,%3}, [%4];"
                 : "=r"(r[0]), "=r"(r[1]), "=r"(r[2]), "=r"(r[3]) : "r"(addr));
}
__device__ __forceinline__ void mma16816(float* c, const uint32_t* a, const uint32_t* b) {
    asm volatile(
        "mma.sync.aligned.m16n8k16.row.col.f32.f16.f16.f32 "
        "{%0,%1,%2,%3}, {%4,%5,%6,%7}, {%8,%9}, {%0,%1,%2,%3};"
        : "+f"(c[0]), "+f"(c[1]), "+f"(c[2]), "+f"(c[3])
        : "r"(a[0]), "r"(a[1]), "r"(a[2]), "r"(a[3]), "r"(b[0]), "r"(b[1]));
}
__device__ __forceinline__ uint32_t packh2(float x, float y) {
    __half2 h = __floats2half2_rn(x, y);
    return *(uint32_t*)&h;
}
__device__ __forceinline__ void cp_async16(uint32_t dst, const void* src) {
    asm volatile("cp.async.cg.shared.global [%0], [%1], 16;" :: "r"(dst), "l"(src) : "memory");
}
__device__ __forceinline__ void cp_commit() {
    asm volatile("cp.async.commit_group;" ::: "memory");
}
__device__ __forceinline__ void cp_wait0() {
    asm volatile("cp.async.wait_group 0;" ::: "memory");
}

// ---------------- tile config ----------------
// A tile: [m=128][RSTRIDE=40 fp16] (32 k + 8 pad), 80B rows.
// B tile: [k=32][136 fp16] (128 n + 8 pad), 272B rows (trans ldmatrix).
#define RSTRIDE 40
#define A_TILE (128 * RSTRIDE * 2)          // 10240 B
#define BROW 136
#define B_TILE (32 * BROW * 2)              // 8704 B
#define STAGEB (A_TILE + B_TILE)            // 18944 B

// MODE: 0 = dense, 1 = gather token (A row = code>>2), 2 = gather code
template <int MODE>
__global__ void __launch_bounds__(256, 2) gemm_mma(
    int a_sel, int lda,
    const float* __restrict__ B1, const float* __restrict__ B2,
    int ldbN, int nsplit, long bstride,
    int c_sel, int ldc, int Ktot, int Mtot)
{
    __shared__ int codes[128];
    __shared__ __align__(16) char stage[2 * STAGEB];   // 37888 B static

    float* C = fbuf_ptr(c_sel);

    int e = blockIdx.z;
    int row0 = blockIdx.y * 128;
    int cnt;
    const int* list = nullptr;
    if (MODE != 0) {
        cnt = g_counts[e];
        if (row0 >= cnt) return;
        list = g_list + e * TT;
    } else {
        cnt = Mtot;
        if (row0 >= cnt) return;
    }

    int tid = threadIdx.x;
    int wid = tid >> 5;
    int lane = tid & 31;

    if (tid < 128) {
        int r = row0 + tid;
        if (r >= cnt) r = cnt - 1;
        codes[tid] = (MODE != 0) ? list[r] : r;
    }
    __syncthreads();

    int n0 = blockIdx.x * 128;
    const float* B;
    if (n0 < nsplit) B = B1 + (size_t)e * bstride + n0;
    else             B = B2 + (size_t)e * bstride + (n0 - nsplit);

    uint32_t sb = smem_u32(stage);

    // A loader: row = tid>>1, 32B chunk = tid&1; two cp.async 16B per tile
    int ar = tid >> 1, akh = tid & 1;
    const __half* a_src;
    {
        int code = codes[ar];
        int arow = (MODE == 1) ? (code >> 2) : code;
        a_src = hbuf_ptr(a_sel) + (size_t)arow * lda + akh * 16;
    }
    uint32_t a_dst = (uint32_t)(ar * RSTRIDE + akh * 16) * 2u;

    // B loader: k row = tid>>3, 16-float chunk = tid&7; 4x LDG.128 fp32 -> 2x STS.128 fp16
    int bk = tid >> 3, bnc = tid & 7;
    const float* b_src = B + (size_t)bk * ldbN + bnc * 16;
    uint32_t b_dst = (uint32_t)A_TILE + (uint32_t)(bk * BROW + bnc * 16) * 2u;

    // compute roles: 8 warps in 2x4, warp tile 64m x 32n
    int wm = (wid >> 2) * 64;
    int wn = (wid & 3) * 32;
    int lrow = lane & 15, lkh = lane >> 4;
    int b_krow = ((lane >> 3) & 1) * 8 + (lane & 7);
    int b_noff = ((lane >> 4) & 1) * 8;

    float c[4][4][4];   // mi (4 x 16m) x ni (4 x 8n) x frag
#pragma unroll
    for (int i = 0; i < 4; i++)
#pragma unroll
        for (int j = 0; j < 4; j++)
#pragma unroll
            for (int q = 0; q < 4; q++) c[i][j][q] = 0.f;

    int nt = Ktot >> 5;  // BK = 32

    float4 bv[4];

    auto fetchA = [&](int t, int slot) {
        uint32_t d = sb + (uint32_t)slot * STAGEB + a_dst;
        const __half* s = a_src + t * 32;
        cp_async16(d, s);
        cp_async16(d + 16, s + 8);
        cp_commit();
    };
    auto loadB = [&](int t) {
        const float* p = b_src + (size_t)(t * 32) * ldbN;
#pragma unroll
        for (int j = 0; j < 4; j++) bv[j] = *(const float4*)(p + j * 4);
    };
    auto storeB = [&](int slot) {
        uint4 o0 = make_uint4(packh2(bv[0].x, bv[0].y), packh2(bv[0].z, bv[0].w),
                              packh2(bv[1].x, bv[1].y), packh2(bv[1].z, bv[1].w));
        uint4 o1 = make_uint4(packh2(bv[2].x, bv[2].y), packh2(bv[2].z, bv[2].w),
                              packh2(bv[3].x, bv[3].y), packh2(bv[3].z, bv[3].w));
        char* p = stage + (size_t)slot * STAGEB + b_dst;
        *(uint4*)(p) = o0;
        *(uint4*)(p + 16) = o1;
    };

    // prologue
    fetchA(0, 0);
    loadB(0);

    for (int t = 0; t < nt; t++) {
        int s = t & 1;
        storeB(s);
        cp_wait0();
        __syncthreads();
        if (t + 1 < nt) {
            fetchA(t + 1, 1 - s);
            loadB(t + 1);
        }

        uint32_t stA = sb + (uint32_t)s * STAGEB;
        uint32_t stB = stA + (uint32_t)A_TILE;

#pragma unroll
        for (int kt = 0; kt < 2; kt++) {
            uint32_t bfrag[4][2];
#pragma unroll
            for (int np = 0; np < 2; np++) {
                uint32_t r[4];
                uint32_t adr = stB + (uint32_t)((kt * 16 + b_krow) * BROW + (wn + np * 16 + b_noff)) * 2u;
                ldsm4t(r, adr);
                bfrag[np * 2 + 0][0] = r[0]; bfrag[np * 2 + 0][1] = r[1];
                bfrag[np * 2 + 1][0] = r[2]; bfrag[np * 2 + 1][1] = r[3];
            }
#pragma unroll
            for (int mi = 0; mi < 4; mi++) {
                uint32_t afrag[4];
                ldsm4(afrag, stA + 2u * (uint32_t)((wm + mi * 16 + lrow) * RSTRIDE + kt * 16 + lkh * 8));
#pragma unroll
                for (int ni = 0; ni < 4; ni++)
                    mma16816(c[mi][ni], afrag, bfrag[ni]);
            }
        }
    }

    // ---- epilogue ----
    int g = lane >> 2, tig = lane & 3;
#pragma unroll
    for (int mi = 0; mi < 4; mi++) {
        int m1 = wm + mi * 16 + g;
        int m2 = m1 + 8;
        bool v1 = (row0 + m1) < cnt;
        bool v2 = (row0 + m2) < cnt;
        int cr1 = codes[m1], cr2 = codes[m2];
        float* p1 = C + (size_t)cr1 * ldc + n0 + wn + tig * 2;
        float* p2 = C + (size_t)cr2 * ldc + n0 + wn + tig * 2;
#pragma unroll
        for (int ni = 0; ni < 4; ni++) {
            if (v1) *(float2*)(p1 + ni * 8) = make_float2(c[mi][ni][0], c[mi][ni][1]);
            if (v2) *(float2*)(p2 + ni * 8) = make_float2(c[mi][ni][2], c[mi][ni][3]);
        }
    }
}

// ---------------- x -> fp16 ----------------
__global__ void convert_x(const float* __restrict__ x) {
    int v = blockIdx.x * blockDim.x + threadIdx.x;
    if (v >= TT * HH / 8) return;
    const float4* xp = (const float4*)x + (size_t)v * 2;
    float4 a = xp[0], b = xp[1];
    uint4 o = make_uint4(packh2(a.x, a.y), packh2(a.z, a.w),
                         packh2(b.x, b.y), packh2(b.z, b.w));
    *(uint4*)(g_x_h + (size_t)v * 8) = o;
}

// ---------------- router ----------------
__global__ void zero_counts_kernel() {
    if (threadIdx.x < EE) g_counts[threadIdx.x] = 0;
}

__global__ void router_kernel(const float* __restrict__ x, const float* __restrict__ gw) {
    int t = blockIdx.x * 4 + (threadIdx.x >> 5);
    int lane = threadIdx.x & 31;
    if (t >= TT) return;
    float acc[EE];
#pragma unroll
    for (int e = 0; e < EE; e++) acc[e] = 0.f;
    const float* xr = x + (size_t)t * HH;
    for (int h = lane; h < HH; h += 32) {
        float xv = xr[h];
#pragma unroll
        for (int e = 0; e < EE; e++) acc[e] += xv * gw[e * HH + h];
    }
#pragma unroll
    for (int e = 0; e < EE; e++) {
#pragma unroll
        for (int o = 16; o > 0; o >>= 1) acc[e] += __shfl_xor_sync(0xffffffffu, acc[e], o);
    }
    if (lane == 0) {
        float m = acc[0];
#pragma unroll
        for (int e = 1; e < EE; e++) m = fmaxf(m, acc[e]);
        float sc[EE];
        float sum = 0.f;
#pragma unroll
        for (int e = 0; e < EE; e++) { sc[e] = expf(acc[e] - m); sum += sc[e]; }
        float inv = 1.f / sum;
#pragma unroll
        for (int e = 0; e < EE; e++) sc[e] *= inv;
        int idx[KTOP]; float w[KTOP]; float wsum = 0.f;
#pragma unroll
        for (int k = 0; k < KTOP; k++) {
            int bi = 0; float bv = -1.f;
#pragma unroll
            for (int e = 0; e < EE; e++) if (sc[e] > bv) { bv = sc[e]; bi = e; }
            idx[k] = bi; w[k] = bv; sc[bi] = -2.f; wsum += bv;
        }
        float winv = 1.f / wsum;
        for (int k = 0; k < KTOP; k++) {
            int code = t * KTOP + k;
            g_tw[code] = w[k] * winv;
            int pos = atomicAdd(&g_counts[idx[k]], 1);
            g_list[idx[k] * TT + pos] = code;
        }
    }
}

// ---------------- elementwise ----------------
__global__ void act_routed_kernel() {
    int v = blockIdx.x * blockDim.x + threadIdx.x;
    const int per = II / 4;
    if (v >= TT * KTOP * per) return;
    int code = v / per, c4 = v - code * per;
    const float* row = g_gu + (size_t)code * (2 * II);
    float4 g4 = *(const float4*)(row + c4 * 4);
    float4 u4 = *(const float4*)(row + II + c4 * 4);
    float w = g_tw[code];
    uint2 o;
    o.x = packh2((g4.x / (1.f + __expf(-g4.x))) * u4.x * w,
                 (g4.y / (1.f + __expf(-g4.y))) * u4.y * w);
    o.y = packh2((g4.z / (1.f + __expf(-g4.z))) * u4.z * w,
                 (g4.w / (1.f + __expf(-g4.w))) * u4.w * w);
    *(uint2*)(g_act_h + (size_t)code * II + c4 * 4) = o;
}

__global__ void act_shared_kernel() {
    int v = blockIdx.x * blockDim.x + threadIdx.x;
    const int per = ISH / 4;
    if (v >= TT * per) return;
    int t = v / per, c4 = v - t * per;
    const float* row = g_sgu + (size_t)t * (2 * ISH);
    float4 g4 = *(const float4*)(row + c4 * 4);
    float4 u4 = *(const float4*)(row + ISH + c4 * 4);
    uint2 o;
    o.x = packh2((g4.x / (1.f + __expf(-g4.x))) * u4.x,
                 (g4.y / (1.f + __expf(-g4.y))) * u4.y);
    o.y = packh2((g4.z / (1.f + __expf(-g4.z))) * u4.z,
                 (g4.w / (1.f + __expf(-g4.w))) * u4.w);
    *(uint2*)(g_shact_h + (size_t)t * ISH + c4 * 4) = o;
}

__global__ void combine_kernel(float* __restrict__ out) {
    int v = blockIdx.x * blockDim.x + threadIdx.x;
    const int per = HH / 4;
    if (v >= TT * per) return;
    int t = v / per, h4 = v - t * per;
    float4 acc = *(const float4*)(g_shdown + (size_t)t * HH + h4 * 4);
#pragma unroll
    for (int k = 0; k < KTOP; k++) {
        float4 d = *(const float4*)(g_downbuf + (size_t)(t * KTOP + k) * HH + h4 * 4);
        acc.x += d.x; acc.y += d.y; acc.z += d.z; acc.w += d.w;
    }
    *(float4*)(out + (size_t)t * HH + h4 * 4) = acc;
}

// ---------------- launch ----------------
extern "C" void kernel_launch(void* const* d_in, const int* in_sizes, int n_in,
                              void* d_out, int out_size) {
    const float* x       = (const float*)d_in[0];
    const float* gate_w  = (const float*)d_in[1];
    const float* w_gate  = (const float*)d_in[2];
    const float* w_up    = (const float*)d_in[3];
    const float* w_down  = (const float*)d_in[4];
    const float* sw_gate = (const float*)d_in[5];
    const float* sw_up   = (const float*)d_in[6];
    const float* sw_down = (const float*)d_in[7];
    float* out = (float*)d_out;

    convert_x<<<(TT * HH / 8 + 255) / 256, 256>>>(x);
    zero_counts_kernel<<<1, 32>>>();
    router_kernel<<<TT / 4, 128>>>(x, gate_w);

    // routed gate+up: A = x_h (gather token), B = w_gate|w_up [k=HH][n=II], C = g_gu
    gemm_mma<1><<<dim3(2 * II / 128, TT / 128, EE), 256>>>(
        2, HH, w_gate, w_up, II, II, (long)HH * II, 0, 2 * II, HH, 0);

    // shared gate+up: A = x_h, B = sw_gate|sw_up [HH][ISH], C = g_sgu
    gemm_mma<0><<<dim3(2 * ISH / 128, TT / 128, 1), 256>>>(
        2, HH, sw_gate, sw_up, ISH, ISH, 0, 3, 2 * ISH, HH, TT);

    act_routed_kernel<<<(TT * KTOP * (II / 4) + 255) / 256, 256>>>();
    act_shared_kernel<<<(TT * (ISH / 4) + 255) / 256, 256>>>();

    // routed down: A = g_act_h (gather code), B = w_down [II][HH], C = g_downbuf
    gemm_mma<2><<<dim3(HH / 128, TT / 128, EE), 256>>>(
        0, II, w_down, w_down, HH, HH, (long)II * HH, 2, HH, II, 0);

    // shared down: A = g_shact_h, B = sw_down [ISH][HH], C = g_shdown
    gemm_mma<0><<<dim3(HH / 128, TT / 128, 1), 256>>>(
        1, ISH, sw_down, sw_down, HH, HH, 0, 5, HH, ISH, TT);

    combine_kernel<<<(TT * (HH / 4) + 255) / 256, 256>>>(out);
}

// round 17
// speedup vs baseline: 1.1242x; 1.1242x over previous
#include <cuda_runtime.h>
#include <cuda_fp16.h>
#include <math.h>
#include <stdint.h>

#define TT 1024
#define HH 2048
#define EE 16
#define KTOP 4
#define II 1408
#define ISH 2816

// ---------------- fp32 scratch ----------------
__device__ float g_gu[(size_t)TT * KTOP * 2 * II];
__device__ float g_downbuf[(size_t)TT * KTOP * HH];
__device__ float g_sgu[(size_t)TT * 2 * ISH];
__device__ float g_shdown[(size_t)TT * HH];
__device__ int   g_counts[EE];
__device__ int   g_list[EE * TT];
__device__ float g_tw[TT * KTOP];

// ---------------- fp16 scratch ----------------
__device__ __half g_act_h[(size_t)TT * KTOP * II];
__device__ __half g_shact_h[(size_t)TT * ISH];
__device__ __half g_x_h[(size_t)TT * HH];
__device__ __half g_wg_h[(size_t)EE * HH * II];    // [e][k=HH][n=II] (native layout)
__device__ __half g_wu_h[(size_t)EE * HH * II];
__device__ __half g_wd_h[(size_t)EE * II * HH];    // [e][k=II][n=HH]
__device__ __half g_swg_h[(size_t)HH * ISH];
__device__ __half g_swu_h[(size_t)HH * ISH];
__device__ __half g_swd_h[(size_t)ISH * HH];

__device__ __forceinline__ float* fbuf_ptr(int sel) {
    switch (sel) {
        case 2: return g_downbuf;
        case 3: return g_sgu;
        case 5: return g_shdown;
        default: return g_gu;
    }
}
__device__ __forceinline__ __half* hbuf_ptr(int sel) {
    switch (sel) {
        case 1: return g_shact_h;
        case 2: return g_x_h;
        case 3: return g_wg_h;
        case 4: return g_wu_h;
        case 5: return g_wd_h;
        case 6: return g_swg_h;
        case 7: return g_swu_h;
        case 8: return g_swd_h;
        default: return g_act_h;
    }
}

// ---------------- helpers ----------------
__device__ __forceinline__ uint32_t smem_u32(const void* p) {
    uint32_t a;
    asm("{ .reg .u64 t; cvta.to.shared.u64 t, %1; cvt.u32.u64 %0, t; }" : "=r"(a) : "l"(p));
    return a;
}
__device__ __forceinline__ void ldsm4(uint32_t* r, uint32_t addr) {
    asm volatile("ldmatrix.sync.aligned.m8n8.x4.shared.b16 {%0,%1,%2,%3}, [%4];"
                 : "=r"(r[0]), "=r"(r[1]), "=r"(r[2]), "=r"(r[3]) : "r"(addr));
}
__device__ __forceinline__ void ldsm4t(uint32_t* r, uint32_t addr) {
    asm volatile("ldmatrix.sync.aligned.m8n8.x4.trans.shared.b16 {%0,%1,%2,%3}, [%4];"
                 : "=r"(r[0]), "=r"(r[1]), "=r"(r[2]), "=r"(r[3]) : "r"(addr));
}
__device__ __forceinline__ void mma16816(float* c, const uint32_t* a, const uint32_t* b) {
    asm volatile(
        "mma.sync.aligned.m16n8k16.row.col.f32.f16.f16.f32 "
        "{%0,%1,%2,%3}, {%4,%5,%6,%7}, {%8,%9}, {%0,%1,%2,%3};"
        : "+f"(c[0]), "+f"(c[1]), "+f"(c[2]), "+f"(c[3])
        : "r"(a[0]), "r"(a[1]), "r"(a[2]), "r"(a[3]), "r"(b[0]), "r"(b[1]));
}
__device__ __forceinline__ uint32_t packh2(float x, float y) {
    __half2 h = __floats2half2_rn(x, y);
    return *(uint32_t*)&h;
}
__device__ __forceinline__ void cp_async16(uint32_t dst, const void* src) {
    asm volatile("cp.async.cg.shared.global [%0], [%1], 16;" :: "r"(dst), "l"(src) : "memory");
}
__device__ __forceinline__ void cp_commit() {
    asm volatile("cp.async.commit_group;" ::: "memory");
}
__device__ __forceinline__ void cp_wait1() {
    asm volatile("cp.async.wait_group 1;" ::: "memory");
}

// ---------------- tile config ----------------
// A tile: [m=128][RSTRIDE=40 fp16] (32 k data + 8 pad), 80B rows -> conflict-free ldmatrix.
// B tile: [k=32][BROW=136 fp16] (128 n data + 8 pad), 272B rows -> conflict-free trans ldmatrix.
#define RSTRIDE 40
#define A_TILE (128 * RSTRIDE * 2)          // 10240 B
#define BROW 136
#define B_TILE (32 * BROW * 2)              // 8704 B
#define STAGEB (A_TILE + B_TILE)            // 18944 B

// MODE: 0 = dense, 1 = gather token (A row = code>>2), 2 = gather code
template <int MODE>
__global__ void __launch_bounds__(512, 2) gemm_mma(
    int a_sel, int lda,
    int b1_sel, int b2_sel,
    int ldbN, int nsplit, long bstride,
    int c_sel, int ldc, int Ktot, int Mtot)
{
    __shared__ int codes[128];
    __shared__ __align__(16) char stage[2 * STAGEB];   // 37888 B static

    float* C = fbuf_ptr(c_sel);

    int e = blockIdx.z;
    int row0 = blockIdx.y * 128;
    int cnt;
    const int* list = nullptr;
    if (MODE != 0) {
        cnt = g_counts[e];
        if (row0 >= cnt) return;
        list = g_list + e * TT;
    } else {
        cnt = Mtot;
        if (row0 >= cnt) return;
    }

    int tid = threadIdx.x;
    int wid = tid >> 5;
    int lane = tid & 31;

    if (tid < 128) {
        int r = row0 + tid;
        if (r >= cnt) r = cnt - 1;
        codes[tid] = (MODE != 0) ? list[r] : r;
    }
    __syncthreads();

    int n0 = blockIdx.x * 128;
    const __half* B;
    {
        int sel = (n0 < nsplit) ? b1_sel : b2_sel;
        int nl = (n0 < nsplit) ? n0 : (n0 - nsplit);
        B = hbuf_ptr(sel) + (size_t)e * bstride + nl;
    }

    uint32_t sb = smem_u32(stage);

    // A loader: 512 chunks = 128 rows x 4 (16B each); one cp.async per thread per tile
    int ar = tid >> 2, ac = tid & 3;
    const __half* a_src;
    {
        int code = codes[ar];
        int arow = (MODE == 1) ? (code >> 2) : code;
        a_src = hbuf_ptr(a_sel) + (size_t)arow * lda + ac * 8;
    }
    uint32_t a_dst = (uint32_t)(ar * RSTRIDE + ac * 8) * 2u;

    // B loader: 512 chunks = 32 k-rows x 16 (16B each); one cp.async per thread per tile
    int bk = tid >> 4, bc = tid & 15;
    const __half* b_src = B + (size_t)bk * ldbN + bc * 8;
    uint32_t b_dst = (uint32_t)A_TILE + (uint32_t)(bk * BROW + bc * 8) * 2u;

    // compute roles: 16 warps in 4x4, warp tile 32m x 32n
    int wm = (wid >> 2) * 32;
    int wn = (wid & 3) * 32;
    int lrow = lane & 15, lkh = lane >> 4;
    int b_krow = ((lane >> 3) & 1) * 8 + (lane & 7);
    int b_noff = ((lane >> 4) & 1) * 8;

    float c[2][4][4];
#pragma unroll
    for (int i = 0; i < 2; i++)
#pragma unroll
        for (int j = 0; j < 4; j++)
#pragma unroll
            for (int q = 0; q < 4; q++) c[i][j][q] = 0.f;

    int nt = Ktot >> 5;  // BK = 32

    auto fetch = [&](int t, int slot) {
        uint32_t base = sb + (uint32_t)slot * STAGEB;
        cp_async16(base + a_dst, a_src + t * 32);
        cp_async16(base + b_dst, b_src + (size_t)(t * 32) * ldbN);
        cp_commit();
    };

    // prologue
    fetch(0, 0);
    fetch(1, 1);

    for (int t = 0; t < nt; t++) {
        int s = t & 1;
        cp_wait1();          // with uniform per-iter commits, forces group for tile t
        __syncthreads();

        uint32_t stA = sb + (uint32_t)s * STAGEB;
        uint32_t stB = stA + (uint32_t)A_TILE;

#pragma unroll
        for (int kt = 0; kt < 2; kt++) {
            uint32_t bfrag[4][2];
#pragma unroll
            for (int np = 0; np < 2; np++) {
                uint32_t r[4];
                uint32_t adr = stB + (uint32_t)((kt * 16 + b_krow) * BROW + (wn + np * 16 + b_noff)) * 2u;
                ldsm4t(r, adr);
                bfrag[np * 2 + 0][0] = r[0]; bfrag[np * 2 + 0][1] = r[1];
                bfrag[np * 2 + 1][0] = r[2]; bfrag[np * 2 + 1][1] = r[3];
            }
#pragma unroll
            for (int mi = 0; mi < 2; mi++) {
                uint32_t afrag[4];
                ldsm4(afrag, stA + 2u * (uint32_t)((wm + mi * 16 + lrow) * RSTRIDE + kt * 16 + lkh * 8));
#pragma unroll
                for (int ni = 0; ni < 4; ni++)
                    mma16816(c[mi][ni], afrag, bfrag[ni]);
            }
        }

        __syncthreads();             // all warps done reading stage s
        // ALWAYS fetch (clamped) so every iteration commits exactly one group;
        // wait_group 1 then provably covers tile t's group. Clamped fetches
        // rewrite identical data into the spent slot (parity differs from the
        // live tail slot) — harmless.
        {
            int tf = t + 2;
            if (tf > nt - 1) tf = nt - 1;
            fetch(tf, s);
        }
    }

    // ---- epilogue ----
    int g = lane >> 2, tig = lane & 3;
#pragma unroll
    for (int mi = 0; mi < 2; mi++) {
        int m1 = wm + mi * 16 + g;
        int m2 = m1 + 8;
        bool v1 = (row0 + m1) < cnt;
        bool v2 = (row0 + m2) < cnt;
        int cr1 = codes[m1], cr2 = codes[m2];
        float* p1 = C + (size_t)cr1 * ldc + n0 + wn + tig * 2;
        float* p2 = C + (size_t)cr2 * ldc + n0 + wn + tig * 2;
#pragma unroll
        for (int ni = 0; ni < 4; ni++) {
            if (v1) *(float2*)(p1 + ni * 8) = make_float2(c[mi][ni][0], c[mi][ni][1]);
            if (v2) *(float2*)(p2 + ni * 8) = make_float2(c[mi][ni][2], c[mi][ni][3]);
        }
    }
}

// ---------------- weight fp32 -> fp16 copy (no transpose) ----------------
__global__ void convert_w(const float* __restrict__ src, long n8, int dsel) {
    long v = (long)blockIdx.x * blockDim.x + threadIdx.x;
    if (v >= n8) return;
    const float4* p = (const float4*)src + v * 2;
    float4 a = p[0], b = p[1];
    uint4 o = make_uint4(packh2(a.x, a.y), packh2(a.z, a.w),
                         packh2(b.x, b.y), packh2(b.z, b.w));
    *(uint4*)(hbuf_ptr(dsel) + v * 8) = o;
}

// ---------------- x -> fp16 ----------------
__global__ void convert_x(const float* __restrict__ x) {
    int v = blockIdx.x * blockDim.x + threadIdx.x;
    if (v >= TT * HH / 8) return;
    const float4* xp = (const float4*)x + (size_t)v * 2;
    float4 a = xp[0], b = xp[1];
    uint4 o = make_uint4(packh2(a.x, a.y), packh2(a.z, a.w),
                         packh2(b.x, b.y), packh2(b.z, b.w));
    *(uint4*)(g_x_h + (size_t)v * 8) = o;
}

// ---------------- router ----------------
__global__ void zero_counts_kernel() {
    if (threadIdx.x < EE) g_counts[threadIdx.x] = 0;
}

__global__ void router_kernel(const float* __restrict__ x, const float* __restrict__ gw) {
    int t = blockIdx.x * 4 + (threadIdx.x >> 5);
    int lane = threadIdx.x & 31;
    if (t >= TT) return;
    float acc[EE];
#pragma unroll
    for (int e = 0; e < EE; e++) acc[e] = 0.f;
    const float* xr = x + (size_t)t * HH;
    for (int h = lane; h < HH; h += 32) {
        float xv = xr[h];
#pragma unroll
        for (int e = 0; e < EE; e++) acc[e] += xv * gw[e * HH + h];
    }
#pragma unroll
    for (int e = 0; e < EE; e++) {
#pragma unroll
        for (int o = 16; o > 0; o >>= 1) acc[e] += __shfl_xor_sync(0xffffffffu, acc[e], o);
    }
    if (lane == 0) {
        float m = acc[0];
#pragma unroll
        for (int e = 1; e < EE; e++) m = fmaxf(m, acc[e]);
        float sc[EE];
        float sum = 0.f;
#pragma unroll
        for (int e = 0; e < EE; e++) { sc[e] = expf(acc[e] - m); sum += sc[e]; }
        float inv = 1.f / sum;
#pragma unroll
        for (int e = 0; e < EE; e++) sc[e] *= inv;
        int idx[KTOP]; float w[KTOP]; float wsum = 0.f;
#pragma unroll
        for (int k = 0; k < KTOP; k++) {
            int bi = 0; float bv = -1.f;
#pragma unroll
            for (int e = 0; e < EE; e++) if (sc[e] > bv) { bv = sc[e]; bi = e; }
            idx[k] = bi; w[k] = bv; sc[bi] = -2.f; wsum += bv;
        }
        float winv = 1.f / wsum;
        for (int k = 0; k < KTOP; k++) {
            int code = t * KTOP + k;
            g_tw[code] = w[k] * winv;
            int pos = atomicAdd(&g_counts[idx[k]], 1);
            g_list[idx[k] * TT + pos] = code;
        }
    }
}

// ---------------- elementwise ----------------
__global__ void act_routed_kernel() {
    int v = blockIdx.x * blockDim.x + threadIdx.x;
    const int per = II / 4;
    if (v >= TT * KTOP * per) return;
    int code = v / per, c4 = v - code * per;
    const float* row = g_gu + (size_t)code * (2 * II);
    float4 g4 = *(const float4*)(row + c4 * 4);
    float4 u4 = *(const float4*)(row + II + c4 * 4);
    float w = g_tw[code];
    uint2 o;
    o.x = packh2((g4.x / (1.f + __expf(-g4.x))) * u4.x * w,
                 (g4.y / (1.f + __expf(-g4.y))) * u4.y * w);
    o.y = packh2((g4.z / (1.f + __expf(-g4.z))) * u4.z * w,
                 (g4.w / (1.f + __expf(-g4.w))) * u4.w * w);
    *(uint2*)(g_act_h + (size_t)code * II + c4 * 4) = o;
}

__global__ void act_shared_kernel() {
    int v = blockIdx.x * blockDim.x + threadIdx.x;
    const int per = ISH / 4;
    if (v >= TT * per) return;
    int t = v / per, c4 = v - t * per;
    const float* row = g_sgu + (size_t)t * (2 * ISH);
    float4 g4 = *(const float4*)(row + c4 * 4);
    float4 u4 = *(const float4*)(row + ISH + c4 * 4);
    uint2 o;
    o.x = packh2((g4.x / (1.f + __expf(-g4.x))) * u4.x,
                 (g4.y / (1.f + __expf(-g4.y))) * u4.y);
    o.y = packh2((g4.z / (1.f + __expf(-g4.z))) * u4.z,
                 (g4.w / (1.f + __expf(-g4.w))) * u4.w);
    *(uint2*)(g_shact_h + (size_t)t * ISH + c4 * 4) = o;
}

__global__ void combine_kernel(float* __restrict__ out) {
    int v = blockIdx.x * blockDim.x + threadIdx.x;
    const int per = HH / 4;
    if (v >= TT * per) return;
    int t = v / per, h4 = v - t * per;
    float4 acc = *(const float4*)(g_shdown + (size_t)t * HH + h4 * 4);
#pragma unroll
    for (int k = 0; k < KTOP; k++) {
        float4 d = *(const float4*)(g_downbuf + (size_t)(t * KTOP + k) * HH + h4 * 4);
        acc.x += d.x; acc.y += d.y; acc.z += d.z; acc.w += d.w;
    }
    *(float4*)(out + (size_t)t * HH + h4 * 4) = acc;
}

// ---------------- launch ----------------
extern "C" void kernel_launch(void* const* d_in, const int* in_sizes, int n_in,
                              void* d_out, int out_size) {
    const float* x       = (const float*)d_in[0];
    const float* gate_w  = (const float*)d_in[1];
    const float* w_gate  = (const float*)d_in[2];
    const float* w_up    = (const float*)d_in[3];
    const float* w_down  = (const float*)d_in[4];
    const float* sw_gate = (const float*)d_in[5];
    const float* sw_up   = (const float*)d_in[6];
    const float* sw_down = (const float*)d_in[7];
    float* out = (float*)d_out;

    const long nw_e = (long)EE * HH * II;    // routed weight elems
    const long nw_s = (long)HH * ISH;        // shared weight elems

    convert_x<<<(TT * HH / 8 + 255) / 256, 256>>>(x);
    convert_w<<<(int)((nw_e / 8 + 255) / 256), 256>>>(w_gate, nw_e / 8, 3);
    convert_w<<<(int)((nw_e / 8 + 255) / 256), 256>>>(w_up, nw_e / 8, 4);
    convert_w<<<(int)((nw_e / 8 + 255) / 256), 256>>>(w_down, nw_e / 8, 5);
    convert_w<<<(int)((nw_s / 8 + 255) / 256), 256>>>(sw_gate, nw_s / 8, 6);
    convert_w<<<(int)((nw_s / 8 + 255) / 256), 256>>>(sw_up, nw_s / 8, 7);
    convert_w<<<(int)((nw_s / 8 + 255) / 256), 256>>>(sw_down, nw_s / 8, 8);

    zero_counts_kernel<<<1, 32>>>();
    router_kernel<<<TT / 4, 128>>>(x, gate_w);

    // routed gate+up: A = x_h (gather token), B = wg_h|wu_h [k=HH][n=II], C = g_gu
    gemm_mma<1><<<dim3(2 * II / 128, TT / 128, EE), 512>>>(
        2, HH, 3, 4, II, II, (long)HH * II, 0, 2 * II, HH, 0);

    // shared gate+up: A = x_h, B = swg_h|swu_h [HH][ISH], C = g_sgu
    gemm_mma<0><<<dim3(2 * ISH / 128, TT / 128, 1), 512>>>(
        2, HH, 6, 7, ISH, ISH, 0, 3, 2 * ISH, HH, TT);

    act_routed_kernel<<<(TT * KTOP * (II / 4) + 255) / 256, 256>>>();
    act_shared_kernel<<<(TT * (ISH / 4) + 255) / 256, 256>>>();

    // routed down: A = g_act_h (gather code), B = wd_h [II][HH], C = g_downbuf
    gemm_mma<2><<<dim3(HH / 128, TT / 128, EE), 512>>>(
        0, II, 5, 5, HH, HH, (long)II * HH, 2, HH, II, 0);

    // shared down: A = g_shact_h, B = swd_h [ISH][HH], C = g_shdown
    gemm_mma<0><<<dim3(HH / 128, TT / 128, 1), 512>>>(
        1, ISH, 8, 8, HH, HH, 0, 5, HH, ISH, TT);

    combine_kernel<<<(TT * (HH / 4) + 255) / 256, 256>>>(out);
}